// round 15
// baseline (speedup 1.0000x reference)
#include <cuda_runtime.h>
#include <cuda_fp16.h>
#include <cstdint>

#define THREADS 768
#define TROWS   768                        // 24 warps * 32 rows
// ---- shared memory layout (bytes) ----
#define WS_OFF    0                        // paired B~ frags: 8jj*5p*4nb*32ln*8B = 40960
#define WH_OFF    40960                    // W_lin hi k16 frags: 2048
#define WL_OFF    43008                    // W_lin lo k16 frags: 2048
#define XP_OFF    45056                    // fp16-packed x tile: 768 rows * 80B
#define XP_PITCH  80                       // 20 words: bank-conflict-free (20g+q distinct)
#define SMEM_BYTES (XP_OFF + TROWS * XP_PITCH)   // 106496

static __device__ __forceinline__ uint32_t smem_u32(const void* p) {
    uint32_t a;
    asm("{ .reg .u64 t; cvta.to.shared.u64 t, %1; cvt.u32.u64 %0, t; }" : "=r"(a) : "l"(p));
    return a;
}
static __device__ __forceinline__ uint32_t hmul2(uint32_t a, uint32_t b) {
    uint32_t d; asm("mul.rn.f16x2 %0, %1, %2;" : "=r"(d) : "r"(a), "r"(b)); return d;
}
static __device__ __forceinline__ uint32_t hpack(float lo, float hi) {
    __half2 h = __floats2half2_rn(lo, hi);
    return *reinterpret_cast<uint32_t*>(&h);
}
static __device__ __forceinline__ void hsplit(float2 v, uint32_t& h, uint32_t& l) {
    __half2 hh = __floats2half2_rn(v.x, v.y);
    float2 b = __half22float2(hh);
    __half2 ll = __floats2half2_rn(v.x - b.x, v.y - b.y);
    h = *reinterpret_cast<uint32_t*>(&hh);
    l = *reinterpret_cast<uint32_t*>(&ll);
}
// splat low/high half of a packed h2 word (PRMT on ALU pipe)
static __device__ __forceinline__ uint32_t prmt_lo(uint32_t w) {
    uint32_t d; asm("prmt.b32 %0, %1, %1, 0x1010;" : "=r"(d) : "r"(w)); return d;
}
static __device__ __forceinline__ uint32_t prmt_hi(uint32_t w) {
    uint32_t d; asm("prmt.b32 %0, %1, %1, 0x3232;" : "=r"(d) : "r"(w)); return d;
}
static __device__ __forceinline__ uint32_t lds32(uint32_t addr) {
    uint32_t d; asm volatile("ld.shared.b32 %0, [%1];" : "=r"(d) : "r"(addr)); return d;
}
// f16 m16n8k16, fp32 accum (linear term)
static __device__ __forceinline__ void mma16(float* acc, uint32_t a0, uint32_t a1,
                                             uint32_t a2, uint32_t a3,
                                             uint32_t b0, uint32_t b1) {
    asm volatile(
        "mma.sync.aligned.m16n8k16.row.col.f32.f16.f16.f32 "
        "{%0,%1,%2,%3}, {%4,%5,%6,%7}, {%8,%9}, {%0,%1,%2,%3};"
        : "+f"(acc[0]), "+f"(acc[1]), "+f"(acc[2]), "+f"(acc[3])
        : "r"(a0), "r"(a1), "r"(a2), "r"(a3), "r"(b0), "r"(b1));
}
// f16 m16n8k16, fp16 accum (bilinear term)
static __device__ __forceinline__ void mma16h(uint32_t* hacc, uint32_t a0, uint32_t a1,
                                              uint32_t a2, uint32_t a3,
                                              uint32_t b0, uint32_t b1) {
    asm volatile(
        "mma.sync.aligned.m16n8k16.row.col.f16.f16.f16.f16 "
        "{%0,%1}, {%2,%3,%4,%5}, {%6,%7}, {%0,%1};"
        : "+r"(hacc[0]), "+r"(hacc[1])
        : "r"(a0), "r"(a1), "r"(a2), "r"(a3), "r"(b0), "r"(b1));
}

// One packed bilinear step, fp16 accumulators.
static __device__ __forceinline__ void bpack_h(
    uint32_t hacc[2][4][2], const uint2* wsp, int jj, int p,
    const uint32_t xp8[4][4], const uint32_t s[4][4],
    int jA, int kA, int jB, int kB)
{
    const uint2* wj = wsp + ((jj * 5 + p) * 4) * 32;
    uint2 bb[4];
    #pragma unroll
    for (int nb = 0; nb < 4; ++nb) bb[nb] = wj[nb * 32];
    #pragma unroll
    for (int f = 0; f < 2; ++f) {
        uint32_t a0 = hmul2(xp8[kA][2*f],   s[jA][2*f]);
        uint32_t a1 = hmul2(xp8[kA][2*f+1], s[jA][2*f+1]);
        uint32_t a2 = hmul2(xp8[kB][2*f],   s[jB][2*f]);
        uint32_t a3 = hmul2(xp8[kB][2*f+1], s[jB][2*f+1]);
        #pragma unroll
        for (int nb = 0; nb < 4; ++nb)
            mma16h(hacc[f][nb], a0, a1, a2, a3, bb[nb].x, bb[nb].y);
    }
}

extern __shared__ __align__(1024) char smem[];

__global__ void __launch_bounds__(THREADS, 1)
nnode_kernel(const float* __restrict__ x, const float* __restrict__ wlin,
             const float* __restrict__ wnl, float* __restrict__ out,
             int ntiles, int nrows) {
    const uint32_t sb = smem_u32(smem);
    const int tid  = threadIdx.x;
    const int wid  = tid >> 5;
    const int lane = tid & 31;
    const int q    = lane & 3;
    const int g    = lane >> 2;
    const int grid = gridDim.x;

    // ===== build paired symmetrized B~ fragments (pairing table from R8) =====
    {
        const int   jgA[5] = {1, 2, 0, 3, 3};
        const int   kcA[5] = {0, 0, 0, 0, 2};
        const float cfA[5] = {1.f, 1.f, 0.5f, 1.f, 1.f};
        const int   jgB[5] = {1, 2, 2, 3, 3};
        const int   kcB[5] = {1, 1, 2, 1, 3};
        const float cfB[5] = {0.5f, 1.f, 0.5f, 1.f, 0.5f};
        uint2* ws = reinterpret_cast<uint2*>(smem + WS_OFF);
        for (int idx = tid; idx < 5120; idx += THREADS) {
            int ln = idx & 31;
            int nb = (idx >> 5) & 3;
            int rest = idx >> 7;
            int p  = rest % 5;
            int jj = rest / 5;
            int n  = nb * 8 + (ln >> 2);
            const float* wn = wnl + n * 1024;
            uint2 v;
            {
                int j = jj + jgA[p] * 8, i0 = kcA[p] * 8 + 2 * (ln & 3);
                float c = cfA[p];
                v.x = hpack(c * (__ldg(wn + i0 * 32 + j)       + __ldg(wn + j * 32 + i0)),
                            c * (__ldg(wn + (i0 + 1) * 32 + j) + __ldg(wn + j * 32 + i0 + 1)));
            }
            {
                int j = jj + jgB[p] * 8, i0 = kcB[p] * 8 + 2 * (ln & 3);
                float c = cfB[p];
                v.y = hpack(c * (__ldg(wn + i0 * 32 + j)       + __ldg(wn + j * 32 + i0)),
                            c * (__ldg(wn + (i0 + 1) * 32 + j) + __ldg(wn + j * 32 + i0 + 1)));
            }
            ws[idx] = v;
        }
    }
    // ===== W_lin hi/lo fp16 k16 fragments =====
    {
        uint2* wh = reinterpret_cast<uint2*>(smem + WH_OFF);
        uint2* wl = reinterpret_cast<uint2*>(smem + WL_OFF);
        for (int idx = tid; idx < 256; idx += THREADS) {
            int kc2 = idx >> 7;
            int nb  = (idx >> 5) & 3;
            int ln  = idx & 31;
            int n   = nb * 8 + (ln >> 2);
            int i0  = kc2 * 16 + 2 * (ln & 3);
            uint32_t h0, l0, h1, l1;
            hsplit(make_float2(__ldg(wlin + i0 * 32 + n), __ldg(wlin + (i0 + 1) * 32 + n)), h0, l0);
            hsplit(make_float2(__ldg(wlin + (i0 + 8) * 32 + n), __ldg(wlin + (i0 + 9) * 32 + n)), h1, l1);
            wh[idx] = make_uint2(h0, h1);
            wl[idx] = make_uint2(l0, l1);
        }
    }

    const int rA = wid * 32 + g;                  // warp owns rows [wid*32, +32)
    const uint2* wsp = reinterpret_cast<const uint2*>(smem + WS_OFF) + lane;
    const uint2* whp = reinterpret_cast<const uint2*>(smem + WH_OFF) + lane;
    const uint2* wlp = reinterpret_cast<const uint2*>(smem + WL_OFF) + lane;
    // per-ridx base addresses into the fp16-packed tile
    uint32_t pr[4];
    #pragma unroll
    for (int ridx = 0; ridx < 4; ++ridx)
        pr[ridx] = sb + XP_OFF + (uint32_t)(rA + 8 * ridx) * XP_PITCH;

    for (int t = blockIdx.x; t < ntiles; t += grid) {
        int vr = nrows - t * TROWS; if (vr > TROWS) vr = TROWS;   // multiple of 32

        // ===== load phase: x fp32 -> packed fp16x2 words in smem =====
        __syncthreads();                      // previous compute done reading
        {
            const float* src = x + (size_t)t * TROWS * 32;
            const int vf = vr * 32;
            #pragma unroll
            for (int s4 = 0; s4 < 8; ++s4) {
                int f = (tid + s4 * THREADS) * 4;        // 4 consecutive floats
                if (f < vf) {
                    float4 v = *reinterpret_cast<const float4*>(src + f);
                    int r = f >> 5, c = f & 31;
                    uint32_t w0 = hpack(v.x, v.y);
                    uint32_t w1 = hpack(v.z, v.w);
                    uint32_t dst = sb + XP_OFF + (uint32_t)(r * XP_PITCH + c * 2);
                    asm volatile("st.shared.v2.b32 [%0], {%1, %2};"
                                 :: "r"(dst), "r"(w0), "r"(w1) : "memory");
                }
            }
        }
        __syncthreads();                      // packed tile visible

        if (wid * 32 < vr) {
            // ---- xp8 fragments: raw LDS.32 of packed words ----
            uint32_t xp8[4][4];
            #pragma unroll
            for (int kc = 0; kc < 4; ++kc)
                #pragma unroll
                for (int ridx = 0; ridx < 4; ++ridx)
                    xp8[kc][ridx] = lds32(pr[ridx] + (uint32_t)((kc * 4 + q) * 4));

            float acc[2][4][4];
            #pragma unroll
            for (int f = 0; f < 2; ++f)
                #pragma unroll
                for (int nb = 0; nb < 4; ++nb)
                    #pragma unroll
                    for (int e = 0; e < 4; ++e) acc[f][nb][e] = 0.f;
            uint32_t hacc[2][4][2];
            #pragma unroll
            for (int f = 0; f < 2; ++f)
                #pragma unroll
                for (int nb = 0; nb < 4; ++nb) {
                    hacc[f][nb][0] = 0u; hacc[f][nb][1] = 0u;
                }

            // ---- linear: xh@Wh + xh@Wl, fp32 accum ----
            #pragma unroll
            for (int kc2 = 0; kc2 < 2; ++kc2) {
                #pragma unroll
                for (int nb = 0; nb < 4; ++nb) {
                    uint2 bh = whp[(kc2 * 4 + nb) * 32];
                    uint2 bl = wlp[(kc2 * 4 + nb) * 32];
                    #pragma unroll
                    for (int f = 0; f < 2; ++f) {
                        mma16(acc[f][nb], xp8[2*kc2][2*f],  xp8[2*kc2][2*f+1],
                                          xp8[2*kc2+1][2*f], xp8[2*kc2+1][2*f+1], bh.x, bh.y);
                        mma16(acc[f][nb], xp8[2*kc2][2*f],  xp8[2*kc2][2*f+1],
                                          xp8[2*kc2+1][2*f], xp8[2*kc2+1][2*f+1], bl.x, bl.y);
                    }
                }
            }

            // ---- bilinear: splats via LDS.32 + PRMT (ALU pipe) ----
            #pragma unroll 2
            for (int jj = 0; jj < 8; ++jj) {
                uint32_t s[4][4];
                #pragma unroll
                for (int jg = 0; jg < 4; ++jg) {
                    const uint32_t woff = (uint32_t)(((jj >> 1) + 4 * jg) * 4);
                    #pragma unroll
                    for (int ridx = 0; ridx < 4; ++ridx) {
                        uint32_t w = lds32(pr[ridx] + woff);
                        s[jg][ridx] = (jj & 1) ? prmt_hi(w) : prmt_lo(w);
                    }
                }
                bpack_h(hacc, wsp, jj, 0, xp8, s, 1, 0, 1, 1);
                bpack_h(hacc, wsp, jj, 1, xp8, s, 2, 0, 2, 1);
                bpack_h(hacc, wsp, jj, 2, xp8, s, 0, 0, 2, 2);
                bpack_h(hacc, wsp, jj, 3, xp8, s, 3, 0, 3, 1);
                bpack_h(hacc, wsp, jj, 4, xp8, s, 3, 2, 3, 3);
            }

            // ---- store: linear(fp32) + bilinear(fp16 unpacked) ----
            #pragma unroll
            for (int f = 0; f < 2; ++f) {
                float* o0 = out + ((size_t)t * TROWS + rA + 16 * f) * 32 + 2 * q;
                float* o1 = o0 + 8 * 32;
                #pragma unroll
                for (int nb = 0; nb < 4; ++nb) {
                    float2 blo = __half22float2(*reinterpret_cast<__half2*>(&hacc[f][nb][0]));
                    float2 bhi = __half22float2(*reinterpret_cast<__half2*>(&hacc[f][nb][1]));
                    *reinterpret_cast<float2*>(o0 + nb * 8) =
                        make_float2(acc[f][nb][0] + blo.x, acc[f][nb][1] + blo.y);
                    *reinterpret_cast<float2*>(o1 + nb * 8) =
                        make_float2(acc[f][nb][2] + bhi.x, acc[f][nb][3] + bhi.y);
                }
            }
        }
    }
}

extern "C" void kernel_launch(void* const* d_in, const int* in_sizes, int n_in,
                              void* d_out, int out_size) {
    const float* x    = (const float*)d_in[0];
    const float* wlin = (const float*)d_in[1];
    const float* wnl  = (const float*)d_in[2];
    float* out = (float*)d_out;

    int nrows  = in_sizes[0] / 32;               // 524288
    int ntiles = (nrows + TROWS - 1) / TROWS;    // 768-row tiles -> 683

    int dev = 0, sms = 148;
    cudaGetDevice(&dev);
    cudaDeviceGetAttribute(&sms, cudaDevAttrMultiProcessorCount, dev);
    if (sms <= 0) sms = 148;
    int grid = sms < ntiles ? sms : ntiles;

    cudaFuncSetAttribute(nnode_kernel, cudaFuncAttributeMaxDynamicSharedMemorySize, SMEM_BYTES);
    nnode_kernel<<<grid, THREADS, SMEM_BYTES>>>(x, wlin, wnl, out, ntiles, nrows);
}

// round 16
// speedup vs baseline: 1.2243x; 1.2243x over previous
#include <cuda_runtime.h>
#include <cuda_fp16.h>
#include <cstdint>

#define THREADS 512
#define TROWS   512
// ---- shared memory layout (bytes) ----
#define WS_OFF    0                        // paired B~ frags: 8jj*5p*4nb*32ln*8B = 40960
#define WH_OFF    40960                    // W_lin hi k16 frags: 2048
#define WL_OFF    43008                    // W_lin lo k16 frags: 2048
#define XS_OFF    45056                    // per-warp x slots: 16 warps * 2 bufs * 4608 B
#define SLOT_B    4608                     // 32 rows * 36 floats * 4
#define XT_STRIDE 36
#define SMEM_BYTES (XS_OFF + 16 * 2 * SLOT_B)   // 192512

static __device__ __forceinline__ uint32_t smem_u32(const void* p) {
    uint32_t a;
    asm("{ .reg .u64 t; cvta.to.shared.u64 t, %1; cvt.u32.u64 %0, t; }" : "=r"(a) : "l"(p));
    return a;
}
static __device__ __forceinline__ uint32_t hsplat(float f) {
    uint32_t d; asm("cvt.rn.f16x2.f32 %0, %1, %1;" : "=r"(d) : "f"(f)); return d;
}
static __device__ __forceinline__ uint32_t hmul2(uint32_t a, uint32_t b) {
    uint32_t d; asm("mul.rn.f16x2 %0, %1, %2;" : "=r"(d) : "r"(a), "r"(b)); return d;
}
static __device__ __forceinline__ uint32_t hpack(float lo, float hi) {
    __half2 h = __floats2half2_rn(lo, hi);
    return *reinterpret_cast<uint32_t*>(&h);
}
static __device__ __forceinline__ void hsplit(float2 v, uint32_t& h, uint32_t& l) {
    __half2 hh = __floats2half2_rn(v.x, v.y);
    float2 b = __half22float2(hh);
    __half2 ll = __floats2half2_rn(v.x - b.x, v.y - b.y);
    h = *reinterpret_cast<uint32_t*>(&hh);
    l = *reinterpret_cast<uint32_t*>(&ll);
}
// f16 m16n8k16, fp32 accum (linear term)
static __device__ __forceinline__ void mma16(float* acc, uint32_t a0, uint32_t a1,
                                             uint32_t a2, uint32_t a3,
                                             uint32_t b0, uint32_t b1) {
    asm volatile(
        "mma.sync.aligned.m16n8k16.row.col.f32.f16.f16.f32 "
        "{%0,%1,%2,%3}, {%4,%5,%6,%7}, {%8,%9}, {%0,%1,%2,%3};"
        : "+f"(acc[0]), "+f"(acc[1]), "+f"(acc[2]), "+f"(acc[3])
        : "r"(a0), "r"(a1), "r"(a2), "r"(a3), "r"(b0), "r"(b1));
}
// f16 m16n8k16, fp16 accum (bilinear term)
static __device__ __forceinline__ void mma16h(uint32_t* hacc, uint32_t a0, uint32_t a1,
                                              uint32_t a2, uint32_t a3,
                                              uint32_t b0, uint32_t b1) {
    asm volatile(
        "mma.sync.aligned.m16n8k16.row.col.f16.f16.f16.f16 "
        "{%0,%1}, {%2,%3,%4,%5}, {%6,%7}, {%0,%1};"
        : "+r"(hacc[0]), "+r"(hacc[1])
        : "r"(a0), "r"(a1), "r"(a2), "r"(a3), "r"(b0), "r"(b1));
}

// One packed bilinear step with batch-loaded B frags, fp16 accumulators.
static __device__ __forceinline__ void bpack_h(
    uint32_t hacc[2][4][2], const uint2 bb[4],
    const uint32_t xp8[4][4], const uint32_t s[4][4],
    int jA, int kA, int jB, int kB)
{
    #pragma unroll
    for (int f = 0; f < 2; ++f) {
        uint32_t a0 = hmul2(xp8[kA][2*f],   s[jA][2*f]);
        uint32_t a1 = hmul2(xp8[kA][2*f+1], s[jA][2*f+1]);
        uint32_t a2 = hmul2(xp8[kB][2*f],   s[jB][2*f]);
        uint32_t a3 = hmul2(xp8[kB][2*f+1], s[jB][2*f+1]);
        #pragma unroll
        for (int nb = 0; nb < 4; ++nb)
            mma16h(hacc[f][nb], a0, a1, a2, a3, bb[nb].x, bb[nb].y);
    }
}

#define CP_ASYNC16(dst, src) \
    asm volatile("cp.async.cg.shared.global [%0], [%1], 16;" :: "r"(dst), "l"(src) : "memory")
#define CP_COMMIT() asm volatile("cp.async.commit_group;" ::: "memory")
#define CP_WAIT1()  asm volatile("cp.async.wait_group 1;" ::: "memory")
#define CP_WAIT0()  asm volatile("cp.async.wait_group 0;" ::: "memory")

extern __shared__ __align__(1024) char smem[];

__global__ void __launch_bounds__(THREADS, 1)
nnode_kernel(const float* __restrict__ x, const float* __restrict__ wlin,
             const float* __restrict__ wnl, float* __restrict__ out, int ntiles) {
    const uint32_t sb = smem_u32(smem);
    const int tid  = threadIdx.x;
    const int wid  = tid >> 5;
    const int lane = tid & 31;
    const int q    = lane & 3;
    const int g    = lane >> 2;
    const int grid = gridDim.x;

    // ===== build paired symmetrized B~ fragments (pairing table from R8) =====
    {
        const int   jgA[5] = {1, 2, 0, 3, 3};
        const int   kcA[5] = {0, 0, 0, 0, 2};
        const float cfA[5] = {1.f, 1.f, 0.5f, 1.f, 1.f};
        const int   jgB[5] = {1, 2, 2, 3, 3};
        const int   kcB[5] = {1, 1, 2, 1, 3};
        const float cfB[5] = {0.5f, 1.f, 0.5f, 1.f, 0.5f};
        uint2* ws = reinterpret_cast<uint2*>(smem + WS_OFF);
        for (int idx = tid; idx < 5120; idx += THREADS) {
            int ln = idx & 31;
            int nb = (idx >> 5) & 3;
            int rest = idx >> 7;
            int p  = rest % 5;
            int jj = rest / 5;
            int n  = nb * 8 + (ln >> 2);
            const float* wn = wnl + n * 1024;
            uint2 v;
            {
                int j = jj + jgA[p] * 8, i0 = kcA[p] * 8 + 2 * (ln & 3);
                float c = cfA[p];
                v.x = hpack(c * (__ldg(wn + i0 * 32 + j)       + __ldg(wn + j * 32 + i0)),
                            c * (__ldg(wn + (i0 + 1) * 32 + j) + __ldg(wn + j * 32 + i0 + 1)));
            }
            {
                int j = jj + jgB[p] * 8, i0 = kcB[p] * 8 + 2 * (ln & 3);
                float c = cfB[p];
                v.y = hpack(c * (__ldg(wn + i0 * 32 + j)       + __ldg(wn + j * 32 + i0)),
                            c * (__ldg(wn + (i0 + 1) * 32 + j) + __ldg(wn + j * 32 + i0 + 1)));
            }
            ws[idx] = v;
        }
    }
    // ===== W_lin hi/lo fp16 k16 fragments =====
    {
        uint2* wh = reinterpret_cast<uint2*>(smem + WH_OFF);
        uint2* wl = reinterpret_cast<uint2*>(smem + WL_OFF);
        for (int idx = tid; idx < 256; idx += THREADS) {
            int kc2 = idx >> 7;
            int nb  = (idx >> 5) & 3;
            int ln  = idx & 31;
            int n   = nb * 8 + (ln >> 2);
            int i0  = kc2 * 16 + 2 * (ln & 3);
            uint32_t h0, l0, h1, l1;
            hsplit(make_float2(__ldg(wlin + i0 * 32 + n), __ldg(wlin + (i0 + 1) * 32 + n)), h0, l0);
            hsplit(make_float2(__ldg(wlin + (i0 + 8) * 32 + n), __ldg(wlin + (i0 + 9) * 32 + n)), h1, l1);
            wh[idx] = make_uint2(h0, h1);
            wl[idx] = make_uint2(l0, l1);
        }
    }
    __syncthreads();        // ONLY CTA-wide barrier: W region ready

    // per-warp x slot bases (double-buffered)
    const uint32_t slot0 = sb + XS_OFF + (uint32_t)wid * (2 * SLOT_B);
    const int rA = wid * 32 + g;
    const uint2* wsp = reinterpret_cast<const uint2*>(smem + WS_OFF) + lane;
    const uint2* whp = reinterpret_cast<const uint2*>(smem + WH_OFF) + lane;
    const uint2* wlp = reinterpret_cast<const uint2*>(smem + WL_OFF) + lane;

    // ===== prologue: this warp prefetches its 32 rows of tile t0 into buf 0 =====
    const int t0 = blockIdx.x;
    if (t0 < ntiles) {
        const float* src = x + ((size_t)t0 * TROWS + wid * 32) * 32;
        #pragma unroll
        for (int s4 = 0; s4 < 8; ++s4) {
            int f = (lane + s4 * 32) * 4;           // [0, 4096) floats = 32 rows
            int r = f >> 5, c = f & 31;
            CP_ASYNC16(slot0 + (uint32_t)(r * XT_STRIDE + c) * 4, src + f);
        }
    }
    CP_COMMIT();

    int buf = 0;
    for (int t = t0; t < ntiles; t += grid) {
        // prefetch this warp's rows of the NEXT tile into the other buffer
        int tn = t + grid;
        if (tn < ntiles) {
            const float* src = x + ((size_t)tn * TROWS + wid * 32) * 32;
            uint32_t dst = slot0 + (uint32_t)(buf ^ 1) * SLOT_B;
            #pragma unroll
            for (int s4 = 0; s4 < 8; ++s4) {
                int f = (lane + s4 * 32) * 4;
                int r = f >> 5, c = f & 31;
                CP_ASYNC16(dst + (uint32_t)(r * XT_STRIDE + c) * 4, src + f);
            }
            CP_COMMIT();
            CP_WAIT1();          // current tile's group (older) complete
        } else {
            CP_WAIT0();
        }
        __syncwarp();            // warp-scope visibility of current buffer

        const float* xt = reinterpret_cast<const float*>(
            smem + (XS_OFF + wid * (2 * SLOT_B) + buf * SLOT_B));
        const float* xr[4] = { xt + (g +  0) * XT_STRIDE, xt + (g +  8) * XT_STRIDE,
                               xt + (g + 16) * XT_STRIDE, xt + (g + 24) * XT_STRIDE };

        // ---- packed fp16 X fragments (hi only) ----
        uint32_t xp8[4][4];
        #pragma unroll
        for (int kc = 0; kc < 4; ++kc) {
            #pragma unroll
            for (int ridx = 0; ridx < 4; ++ridx) {
                float2 v = *reinterpret_cast<const float2*>(xr[ridx] + kc * 8 + 2 * q);
                xp8[kc][ridx] = hpack(v.x, v.y);
            }
        }

        float acc[2][4][4];
        #pragma unroll
        for (int f = 0; f < 2; ++f)
            #pragma unroll
            for (int nb = 0; nb < 4; ++nb)
                #pragma unroll
                for (int e = 0; e < 4; ++e) acc[f][nb][e] = 0.f;
        uint32_t hacc[2][4][2];
        #pragma unroll
        for (int f = 0; f < 2; ++f)
            #pragma unroll
            for (int nb = 0; nb < 4; ++nb) {
                hacc[f][nb][0] = 0u; hacc[f][nb][1] = 0u;
            }

        // ---- linear: xh@Wh + xh@Wl, fp32 accum ----
        #pragma unroll
        for (int kc2 = 0; kc2 < 2; ++kc2) {
            #pragma unroll
            for (int nb = 0; nb < 4; ++nb) {
                uint2 bh = whp[(kc2 * 4 + nb) * 32];
                uint2 bl = wlp[(kc2 * 4 + nb) * 32];
                #pragma unroll
                for (int f = 0; f < 2; ++f) {
                    mma16(acc[f][nb], xp8[2*kc2][2*f],  xp8[2*kc2][2*f+1],
                                      xp8[2*kc2+1][2*f], xp8[2*kc2+1][2*f+1], bh.x, bh.y);
                    mma16(acc[f][nb], xp8[2*kc2][2*f],  xp8[2*kc2][2*f+1],
                                      xp8[2*kc2+1][2*f], xp8[2*kc2+1][2*f+1], bl.x, bl.y);
                }
            }
        }

        // ---- bilinear: fp16-acc mmas, batch-loaded B frags ----
        #pragma unroll 2
        for (int jj = 0; jj < 8; ++jj) {
            uint32_t s[4][4];
            #pragma unroll
            for (int jg = 0; jg < 4; ++jg)
                #pragma unroll
                for (int ridx = 0; ridx < 4; ++ridx)
                    s[jg][ridx] = hsplat(xr[ridx][jj + jg * 8]);

            uint2 bb[5][4];
            #pragma unroll
            for (int p = 0; p < 5; ++p)
                #pragma unroll
                for (int nb = 0; nb < 4; ++nb)
                    bb[p][nb] = wsp[((jj * 5 + p) * 4 + nb) * 32];

            bpack_h(hacc, bb[0], xp8, s, 1, 0, 1, 1);
            bpack_h(hacc, bb[1], xp8, s, 2, 0, 2, 1);
            bpack_h(hacc, bb[2], xp8, s, 0, 0, 2, 2);
            bpack_h(hacc, bb[3], xp8, s, 3, 0, 3, 1);
            bpack_h(hacc, bb[4], xp8, s, 3, 2, 3, 3);
        }

        // ---- store: linear(fp32) + bilinear(fp16 unpacked) ----
        #pragma unroll
        for (int f = 0; f < 2; ++f) {
            float* o0 = out + ((size_t)t * TROWS + rA + 16 * f) * 32 + 2 * q;
            float* o1 = o0 + 8 * 32;
            #pragma unroll
            for (int nb = 0; nb < 4; ++nb) {
                float2 blo = __half22float2(*reinterpret_cast<__half2*>(&hacc[f][nb][0]));
                float2 bhi = __half22float2(*reinterpret_cast<__half2*>(&hacc[f][nb][1]));
                *reinterpret_cast<float2*>(o0 + nb * 8) =
                    make_float2(acc[f][nb][0] + blo.x, acc[f][nb][1] + blo.y);
                *reinterpret_cast<float2*>(o1 + nb * 8) =
                    make_float2(acc[f][nb][2] + bhi.x, acc[f][nb][3] + bhi.y);
            }
        }
        buf ^= 1;
    }
}

extern "C" void kernel_launch(void* const* d_in, const int* in_sizes, int n_in,
                              void* d_out, int out_size) {
    const float* x    = (const float*)d_in[0];
    const float* wlin = (const float*)d_in[1];
    const float* wnl  = (const float*)d_in[2];
    float* out = (float*)d_out;

    int ntiles = in_sizes[0] / 16384;       // 512-row tiles; 1024 for B=524288

    int dev = 0, sms = 148;
    cudaGetDevice(&dev);
    cudaDeviceGetAttribute(&sms, cudaDevAttrMultiProcessorCount, dev);
    if (sms <= 0) sms = 148;
    int grid = sms < ntiles ? sms : ntiles;

    cudaFuncSetAttribute(nnode_kernel, cudaFuncAttributeMaxDynamicSharedMemorySize, SMEM_BYTES);
    nnode_kernel<<<grid, THREADS, SMEM_BYTES>>>(x, wlin, wnl, out, ntiles);
}